// round 11
// baseline (speedup 1.0000x reference)
#include <cuda_runtime.h>
#include <cuda_bf16.h>
#include <cstdint>

#define NU 50000
#define NI 50000
#define NE 800000
#define HD 128
#define NN (NI + NU)

typedef unsigned long long u64;

// ---------------- f32x2 packed-FMA helpers (Blackwell FFMA2) ----------------
__device__ __forceinline__ u64 pk2(float v) {
    u64 r; asm("mov.b64 %0, {%1,%1};" : "=l"(r) : "f"(v)); return r;
}
__device__ __forceinline__ void fma2(u64& d, u64 a, u64 b) {
    asm("fma.rn.f32x2 %0, %1, %2, %3;" : "=l"(d) : "l"(a), "l"(b), "l"(d));
}
__device__ __forceinline__ float2 up2(u64 v) {
    float2 f; asm("mov.b64 {%0,%1}, %2;" : "=f"(f.x), "=f"(f.y) : "l"(v)); return f;
}

// ---------------- device scratch ----------------
__device__ __align__(16) float g_hu [(size_t)NU * HD];
__device__ __align__(16) float g_hi [(size_t)NI * HD];
__device__ __align__(16) float g_hu2[(size_t)NU * HD];
__device__ __align__(16) float g_hi2[(size_t)NI * HD];
__device__ __align__(16) float g_aggi [(size_t)NI * HD];
__device__ __align__(16) float g_aggu [(size_t)NU * HD];
__device__ __align__(16) float g_aggu2[(size_t)NU * HD];

__device__ __align__(16) int g_deg[NN];         // [deg_item | deg_user]
__device__ __align__(16) int g_rowptr[NN + 1];  // combined CSR rowptr
__device__ __align__(16) int g_fill[NN];        // fill cursors
__device__ __align__(16) int g_bsums[128];      // block sums for 2-level scan
__device__ __align__(16) int g_esrc[2 * NE];    // combined grouped edge sources

// ---------------- zero ----------------
__global__ void zero_kernel(float4* __restrict__ p, int n4) {
    int i = blockIdx.x * blockDim.x + threadIdx.x;
    if (i < n4) p[i] = make_float4(0.f, 0.f, 0.f, 0.f);
}

// ---------------- CSR: histogram over both relations (2 edges/thread) ----------------
__global__ void hist2_kernel(const int* __restrict__ ei_a, const int* __restrict__ ei_b,
                             int* __restrict__ deg)
{
    int t = blockIdx.x * blockDim.x + threadIdx.x;      // 0 .. NE-1 (NE even)
    if (t < NE / 2) {
        int2 d = *reinterpret_cast<const int2*>(ei_a + NE + 2 * t);
        atomicAdd(&deg[d.x], 1);
        atomicAdd(&deg[d.y], 1);
    } else if (t < NE) {
        int2 d = *reinterpret_cast<const int2*>(ei_b + NE + 2 * (t - NE / 2));
        atomicAdd(&deg[NI + d.x], 1);
        atomicAdd(&deg[NI + d.y], 1);
    }
}

// ---------------- CSR: two-level scan ----------------
__global__ void __launch_bounds__(1024) scan1_kernel(
    const int* __restrict__ deg, int* __restrict__ rowptr, int* __restrict__ bsums, int n)
{
    __shared__ int ws[32];
    const int tid = threadIdx.x, lane = tid & 31, wid = tid >> 5;
    int i = blockIdx.x * 1024 + tid;
    int v = (i < n) ? deg[i] : 0;
    int x = v;
#pragma unroll
    for (int off = 1; off < 32; off <<= 1) {
        int y = __shfl_up_sync(0xffffffffu, x, off);
        if (lane >= off) x += y;
    }
    if (lane == 31) ws[wid] = x;
    __syncthreads();
    if (tid < 32) {
        int s = ws[tid];
#pragma unroll
        for (int off = 1; off < 32; off <<= 1) {
            int y = __shfl_up_sync(0xffffffffu, s, off);
            if (tid >= off) s += y;
        }
        ws[tid] = s;
    }
    __syncthreads();
    int prev = wid ? ws[wid - 1] : 0;
    if (i < n) rowptr[i] = prev + x - v;
    if (tid == 1023) bsums[blockIdx.x] = prev + x;
}

__global__ void __launch_bounds__(1024) scan2_kernel(int* __restrict__ data, int n) {
    __shared__ int ws[32];
    const int tid = threadIdx.x, lane = tid & 31, wid = tid >> 5;
    int v = (tid < n) ? data[tid] : 0;
    int x = v;
#pragma unroll
    for (int off = 1; off < 32; off <<= 1) {
        int y = __shfl_up_sync(0xffffffffu, x, off);
        if (lane >= off) x += y;
    }
    if (lane == 31) ws[wid] = x;
    __syncthreads();
    if (tid < 32) {
        int s = ws[tid];
#pragma unroll
        for (int off = 1; off < 32; off <<= 1) {
            int y = __shfl_up_sync(0xffffffffu, s, off);
            if (tid >= off) s += y;
        }
        ws[tid] = s;
    }
    __syncthreads();
    int prev = wid ? ws[wid - 1] : 0;
    if (tid < n) data[tid] = prev + x - v;
}

__global__ void scan3_kernel(int* __restrict__ rowptr, int* __restrict__ fill,
                             const int* __restrict__ bsums, int n, int total)
{
    int i = blockIdx.x * blockDim.x + threadIdx.x;
    if (i < n) {
        int v = rowptr[i] + bsums[i >> 10];
        rowptr[i] = v;
        fill[i] = v;
    }
    if (i == 0) rowptr[n] = total;
}

// ---------------- CSR: fill edge-source buckets (2 edges/thread) ----------------
__global__ void fill2_kernel(const int* __restrict__ ei_a, const int* __restrict__ ei_b,
                             int* __restrict__ cursor, int* __restrict__ esrc)
{
    int t = blockIdx.x * blockDim.x + threadIdx.x;
    if (t < NE / 2) {
        int e = 2 * t;
        int2 d = *reinterpret_cast<const int2*>(ei_a + NE + e);
        int2 s = *reinterpret_cast<const int2*>(ei_a + e);
        esrc[atomicAdd(&cursor[d.x], 1)] = s.x;
        esrc[atomicAdd(&cursor[d.y], 1)] = s.y;
    } else if (t < NE) {
        int e = 2 * (t - NE / 2);
        int2 d = *reinterpret_cast<const int2*>(ei_b + NE + e);
        int2 s = *reinterpret_cast<const int2*>(ei_b + e);
        esrc[atomicAdd(&cursor[NI + d.x], 1)] = s.x;
        esrc[atomicAdd(&cursor[NI + d.y], 1)] = s.y;
    }
}

// ---------------- gather mean: one warp per dst node ----------------
__global__ void __launch_bounds__(256) gather_mean_kernel(
    const float* __restrict__ src_feat, const int* __restrict__ rowptr,
    const int* __restrict__ esrc, float* __restrict__ agg, int n)
{
    int node = (blockIdx.x * blockDim.x + threadIdx.x) >> 5;
    int lane = threadIdx.x & 31;
    if (node >= n) return;
    int beg = __ldg(&rowptr[node]);
    int end = __ldg(&rowptr[node + 1]);
    float4 acc = make_float4(0.f, 0.f, 0.f, 0.f);
    int e = beg;
    for (; e + 4 <= end; e += 4) {
        int s0 = __ldg(&esrc[e]);
        int s1 = __ldg(&esrc[e + 1]);
        int s2 = __ldg(&esrc[e + 2]);
        int s3 = __ldg(&esrc[e + 3]);
        float4 v0 = reinterpret_cast<const float4*>(src_feat + (size_t)s0 * HD)[lane];
        float4 v1 = reinterpret_cast<const float4*>(src_feat + (size_t)s1 * HD)[lane];
        float4 v2 = reinterpret_cast<const float4*>(src_feat + (size_t)s2 * HD)[lane];
        float4 v3 = reinterpret_cast<const float4*>(src_feat + (size_t)s3 * HD)[lane];
        acc.x += (v0.x + v1.x) + (v2.x + v3.x);
        acc.y += (v0.y + v1.y) + (v2.y + v3.y);
        acc.z += (v0.z + v1.z) + (v2.z + v3.z);
        acc.w += (v0.w + v1.w) + (v2.w + v3.w);
    }
    for (; e < end; e++) {
        int s = __ldg(&esrc[e]);
        float4 v = reinterpret_cast<const float4*>(src_feat + (size_t)s * HD)[lane];
        acc.x += v.x; acc.y += v.y; acc.z += v.z; acc.w += v.w;
    }
    float inv = 1.0f / fmaxf((float)(end - beg), 1.0f);
    acc.x *= inv; acc.y *= inv; acc.z *= inv; acc.w *= inv;
    reinterpret_cast<float4*>(agg + (size_t)node * HD)[lane] = acc;
}

// ---------------- fused SAGE combine (FFMA2), out-of-place ----------------
// h_out[r] = relu( L2norm(agg[r] @ Wl + bl + h_in[r] @ Wr) ) + h_in[r]
__global__ void __launch_bounds__(128) combine_kernel(
    const float* __restrict__ agg, const float* __restrict__ h_in,
    float* __restrict__ h_out,
    const float* __restrict__ wl, const float* __restrict__ bl,
    const float* __restrict__ wr, int n)
{
    __shared__ __align__(16) float As[16 * 64];
    __shared__ __align__(16) float Xs[16 * 64];
    __shared__ __align__(16) float Wls[16 * 128];
    __shared__ __align__(16) float Wrs[16 * 128];

    const int tid  = threadIdx.x;
    const int tx   = tid & 15;
    const int ty   = tid >> 4;
    const int row0 = blockIdx.x * 64;

    u64 acc[8][4];
#pragma unroll
    for (int i = 0; i < 8; i++)
#pragma unroll
        for (int j = 0; j < 4; j++) acc[i][j] = 0ull;

    const int lrow  = tid >> 1;
    const int lhalf = tid & 1;
    const int grow  = min(row0 + lrow, n - 1);

    for (int kc = 0; kc < 8; kc++) {
        const int k0 = kc * 16;
        {
            const float4* sl = reinterpret_cast<const float4*>(wl + k0 * 128);
            const float4* sr = reinterpret_cast<const float4*>(wr + k0 * 128);
            float4* dl = reinterpret_cast<float4*>(Wls);
            float4* dr = reinterpret_cast<float4*>(Wrs);
#pragma unroll
            for (int i = 0; i < 4; i++) {
                dl[tid + i * 128] = sl[tid + i * 128];
                dr[tid + i * 128] = sr[tid + i * 128];
            }
        }
        {
            const float* ap = agg  + (size_t)grow * HD + k0 + lhalf * 8;
            const float* xp = h_in + (size_t)grow * HD + k0 + lhalf * 8;
            float4 a0 = *reinterpret_cast<const float4*>(ap);
            float4 a1 = *reinterpret_cast<const float4*>(ap + 4);
            float4 x0 = *reinterpret_cast<const float4*>(xp);
            float4 x1 = *reinterpret_cast<const float4*>(xp + 4);
            int kb = lhalf * 8;
            As[(kb + 0) * 64 + lrow] = a0.x;
            As[(kb + 1) * 64 + lrow] = a0.y;
            As[(kb + 2) * 64 + lrow] = a0.z;
            As[(kb + 3) * 64 + lrow] = a0.w;
            As[(kb + 4) * 64 + lrow] = a1.x;
            As[(kb + 5) * 64 + lrow] = a1.y;
            As[(kb + 6) * 64 + lrow] = a1.z;
            As[(kb + 7) * 64 + lrow] = a1.w;
            Xs[(kb + 0) * 64 + lrow] = x0.x;
            Xs[(kb + 1) * 64 + lrow] = x0.y;
            Xs[(kb + 2) * 64 + lrow] = x0.z;
            Xs[(kb + 3) * 64 + lrow] = x0.w;
            Xs[(kb + 4) * 64 + lrow] = x1.x;
            Xs[(kb + 5) * 64 + lrow] = x1.y;
            Xs[(kb + 6) * 64 + lrow] = x1.z;
            Xs[(kb + 7) * 64 + lrow] = x1.w;
        }
        __syncthreads();

#pragma unroll 2
        for (int k = 0; k < 16; k++) {
            float4 a0 = *reinterpret_cast<float4*>(&As[k * 64 + ty * 8]);
            float4 a1 = *reinterpret_cast<float4*>(&As[k * 64 + ty * 8 + 4]);
            float4 x0 = *reinterpret_cast<float4*>(&Xs[k * 64 + ty * 8]);
            float4 x1 = *reinterpret_cast<float4*>(&Xs[k * 64 + ty * 8 + 4]);
            ulonglong2 L0 = *reinterpret_cast<ulonglong2*>(&Wls[k * 128 + tx * 8]);
            ulonglong2 L1 = *reinterpret_cast<ulonglong2*>(&Wls[k * 128 + tx * 8 + 4]);
            ulonglong2 R0 = *reinterpret_cast<ulonglong2*>(&Wrs[k * 128 + tx * 8]);
            ulonglong2 R1 = *reinterpret_cast<ulonglong2*>(&Wrs[k * 128 + tx * 8 + 4]);
            u64 lv[4] = {L0.x, L0.y, L1.x, L1.y};
            u64 rv[4] = {R0.x, R0.y, R1.x, R1.y};
            float av[8] = {a0.x, a0.y, a0.z, a0.w, a1.x, a1.y, a1.z, a1.w};
            float xv[8] = {x0.x, x0.y, x0.z, x0.w, x1.x, x1.y, x1.z, x1.w};
#pragma unroll
            for (int i = 0; i < 8; i++) {
                u64 ap2 = pk2(av[i]);
                u64 xp2 = pk2(xv[i]);
#pragma unroll
                for (int j = 0; j < 4; j++) {
                    fma2(acc[i][j], ap2, lv[j]);
                    fma2(acc[i][j], xp2, rv[j]);
                }
            }
        }
        __syncthreads();
    }

    float bias[8];
#pragma unroll
    for (int j = 0; j < 8; j++) bias[j] = __ldg(&bl[tx * 8 + j]);

#pragma unroll
    for (int i = 0; i < 8; i++) {
        float v[8];
        float ss = 0.f;
#pragma unroll
        for (int j = 0; j < 4; j++) {
            float2 t = up2(acc[i][j]);
            v[2 * j]     = t.x + bias[2 * j];
            v[2 * j + 1] = t.y + bias[2 * j + 1];
            ss = fmaf(v[2 * j], v[2 * j], ss);
            ss = fmaf(v[2 * j + 1], v[2 * j + 1], ss);
        }
#pragma unroll
        for (int m = 8; m >= 1; m >>= 1)
            ss += __shfl_xor_sync(0xffffffffu, ss, m, 16);
        float inv = 1.0f / fmaxf(sqrtf(ss), 1e-12f);
        int gr = row0 + ty * 8 + i;
        if (gr < n) {
            const float* hip = h_in + (size_t)gr * HD + tx * 8;
            float4 h0 = *reinterpret_cast<const float4*>(hip);
            float4 h1 = *reinterpret_cast<const float4*>(hip + 4);
            float o[8] = {h0.x, h0.y, h0.z, h0.w, h1.x, h1.y, h1.z, h1.w};
#pragma unroll
            for (int j = 0; j < 8; j++) o[j] += fmaxf(v[j] * inv, 0.0f);
            float* hop = h_out + (size_t)gr * HD + tx * 8;
            *reinterpret_cast<float4*>(hop)     = make_float4(o[0], o[1], o[2], o[3]);
            *reinterpret_cast<float4*>(hop + 4) = make_float4(o[4], o[5], o[6], o[7]);
        }
    }
}

// ---------------- register-tiled dense + relu (FFMA2) — encoders ----------------
template<int K, int N>
__global__ void __launch_bounds__(128) mlp_relu_kernel(
    const float* __restrict__ x, const float* __restrict__ W,
    const float* __restrict__ b, float* __restrict__ out, int n)
{
    constexpr int TX = N / 8;
    constexpr int TY = 128 / TX;
    constexpr int BM = TY * 8;
    __shared__ __align__(16) float Xs[16 * BM];
    __shared__ __align__(16) float Ws[16 * N];

    const int tid  = threadIdx.x;
    const int tx   = tid % TX;
    const int ty   = tid / TX;
    const int row0 = blockIdx.x * BM;

    u64 acc[8][4];
#pragma unroll
    for (int i = 0; i < 8; i++)
#pragma unroll
        for (int j = 0; j < 4; j++) acc[i][j] = 0ull;

#pragma unroll 1
    for (int kc = 0; kc < K / 16; kc++) {
        const int k0 = kc * 16;
#pragma unroll
        for (int i = tid; i < 16 * N / 4; i += 128)
            reinterpret_cast<float4*>(Ws)[i] =
                reinterpret_cast<const float4*>(W + (size_t)k0 * N)[i];
#pragma unroll
        for (int idx = tid; idx < BM * 2; idx += 128) {
            int r = idx >> 1, half = idx & 1;
            int gr = min(row0 + r, n - 1);
            const float* xp = x + (size_t)gr * K + k0 + half * 8;
            float4 x0 = *reinterpret_cast<const float4*>(xp);
            float4 x1 = *reinterpret_cast<const float4*>(xp + 4);
            int kb = half * 8;
            Xs[(kb + 0) * BM + r] = x0.x;
            Xs[(kb + 1) * BM + r] = x0.y;
            Xs[(kb + 2) * BM + r] = x0.z;
            Xs[(kb + 3) * BM + r] = x0.w;
            Xs[(kb + 4) * BM + r] = x1.x;
            Xs[(kb + 5) * BM + r] = x1.y;
            Xs[(kb + 6) * BM + r] = x1.z;
            Xs[(kb + 7) * BM + r] = x1.w;
        }
        __syncthreads();

#pragma unroll 2
        for (int k = 0; k < 16; k++) {
            float4 a0 = *reinterpret_cast<float4*>(&Xs[k * BM + ty * 8]);
            float4 a1 = *reinterpret_cast<float4*>(&Xs[k * BM + ty * 8 + 4]);
            ulonglong2 W0 = *reinterpret_cast<ulonglong2*>(&Ws[k * N + tx * 8]);
            ulonglong2 W1 = *reinterpret_cast<ulonglong2*>(&Ws[k * N + tx * 8 + 4]);
            u64 wv[4] = {W0.x, W0.y, W1.x, W1.y};
            float av[8] = {a0.x, a0.y, a0.z, a0.w, a1.x, a1.y, a1.z, a1.w};
#pragma unroll
            for (int i = 0; i < 8; i++) {
                u64 ap2 = pk2(av[i]);
#pragma unroll
                for (int j = 0; j < 4; j++)
                    fma2(acc[i][j], ap2, wv[j]);
            }
        }
        __syncthreads();
    }

    float bias[8];
#pragma unroll
    for (int j = 0; j < 8; j++) bias[j] = __ldg(&b[tx * 8 + j]);

#pragma unroll
    for (int i = 0; i < 8; i++) {
        int gr = row0 + ty * 8 + i;
        if (gr < n) {
            float o[8];
#pragma unroll
            for (int j = 0; j < 4; j++) {
                float2 t = up2(acc[i][j]);
                o[2 * j]     = fmaxf(t.x + bias[2 * j], 0.0f);
                o[2 * j + 1] = fmaxf(t.y + bias[2 * j + 1], 0.0f);
            }
            float* op = out + (size_t)gr * N + tx * 8;
            *reinterpret_cast<float4*>(op)     = make_float4(o[0], o[1], o[2], o[3]);
            *reinterpret_cast<float4*>(op + 4) = make_float4(o[4], o[5], o[6], o[7]);
        }
    }
}

// ---------------- fused head: out = relu(hu @ w1 + b1) @ w2 + b2 ----------------
// BM=128 rows/block, 128 threads. Stage z (BM x 64) in smem, then z @ w2.
__global__ void __launch_bounds__(128) head_fused_kernel(
    const float* __restrict__ x, const float* __restrict__ w1,
    const float* __restrict__ b1, const float* __restrict__ w2,
    const float* __restrict__ b2, float* __restrict__ out, int n)
{
    constexpr int N = 64, TX = 8, BM = 128;
    __shared__ __align__(16) float Xs[16 * BM];
    __shared__ __align__(16) float Ws[16 * N];
    __shared__ __align__(16) float Zs[BM * N];
    __shared__ __align__(16) float W2s[64 * 8];

    const int tid  = threadIdx.x;
    const int tx   = tid % TX;
    const int ty   = tid / TX;
    const int row0 = blockIdx.x * BM;

    // stage w2 once
#pragma unroll
    for (int i = tid; i < 64 * 8 / 4; i += 128)
        reinterpret_cast<float4*>(W2s)[i] = reinterpret_cast<const float4*>(w2)[i];

    u64 acc[8][4];
#pragma unroll
    for (int i = 0; i < 8; i++)
#pragma unroll
        for (int j = 0; j < 4; j++) acc[i][j] = 0ull;

#pragma unroll 1
    for (int kc = 0; kc < 8; kc++) {
        const int k0 = kc * 16;
#pragma unroll
        for (int i = tid; i < 16 * N / 4; i += 128)
            reinterpret_cast<float4*>(Ws)[i] =
                reinterpret_cast<const float4*>(w1 + (size_t)k0 * N)[i];
#pragma unroll
        for (int idx = tid; idx < BM * 2; idx += 128) {
            int r = idx >> 1, half = idx & 1;
            int gr = min(row0 + r, n - 1);
            const float* xp = x + (size_t)gr * HD + k0 + half * 8;
            float4 x0 = *reinterpret_cast<const float4*>(xp);
            float4 x1 = *reinterpret_cast<const float4*>(xp + 4);
            int kb = half * 8;
            Xs[(kb + 0) * BM + r] = x0.x;
            Xs[(kb + 1) * BM + r] = x0.y;
            Xs[(kb + 2) * BM + r] = x0.z;
            Xs[(kb + 3) * BM + r] = x0.w;
            Xs[(kb + 4) * BM + r] = x1.x;
            Xs[(kb + 5) * BM + r] = x1.y;
            Xs[(kb + 6) * BM + r] = x1.z;
            Xs[(kb + 7) * BM + r] = x1.w;
        }
        __syncthreads();

#pragma unroll 2
        for (int k = 0; k < 16; k++) {
            float4 a0 = *reinterpret_cast<float4*>(&Xs[k * BM + ty * 8]);
            float4 a1 = *reinterpret_cast<float4*>(&Xs[k * BM + ty * 8 + 4]);
            ulonglong2 W0 = *reinterpret_cast<ulonglong2*>(&Ws[k * N + tx * 8]);
            ulonglong2 W1 = *reinterpret_cast<ulonglong2*>(&Ws[k * N + tx * 8 + 4]);
            u64 wv[4] = {W0.x, W0.y, W1.x, W1.y};
            float av[8] = {a0.x, a0.y, a0.z, a0.w, a1.x, a1.y, a1.z, a1.w};
#pragma unroll
            for (int i = 0; i < 8; i++) {
                u64 ap2 = pk2(av[i]);
#pragma unroll
                for (int j = 0; j < 4; j++)
                    fma2(acc[i][j], ap2, wv[j]);
            }
        }
        __syncthreads();
    }

    float bias[8];
#pragma unroll
    for (int j = 0; j < 8; j++) bias[j] = __ldg(&b1[tx * 8 + j]);

    // write relu(z) into smem
#pragma unroll
    for (int i = 0; i < 8; i++) {
        int r = ty * 8 + i;
        float o[8];
#pragma unroll
        for (int j = 0; j < 4; j++) {
            float2 t = up2(acc[i][j]);
            o[2 * j]     = fmaxf(t.x + bias[2 * j], 0.0f);
            o[2 * j + 1] = fmaxf(t.y + bias[2 * j + 1], 0.0f);
        }
        float* zp = &Zs[r * N + tx * 8];
        *reinterpret_cast<float4*>(zp)     = make_float4(o[0], o[1], o[2], o[3]);
        *reinterpret_cast<float4*>(zp + 4) = make_float4(o[4], o[5], o[6], o[7]);
    }
    __syncthreads();

    // second layer: each thread handles one row (128 threads = BM rows)
    int gr = row0 + tid;
    if (gr < n) {
        float a2[8];
#pragma unroll
        for (int j = 0; j < 8; j++) a2[j] = __ldg(&b2[j]);
        const float* zr = &Zs[tid * N];
#pragma unroll
        for (int k = 0; k < 64; k++) {
            float zv = zr[k];
#pragma unroll
            for (int j = 0; j < 8; j++)
                a2[j] = fmaf(zv, W2s[k * 8 + j], a2[j]);
        }
        float* op = out + (size_t)gr * 8;
        *reinterpret_cast<float4*>(op)     = make_float4(a2[0], a2[1], a2[2], a2[3]);
        *reinterpret_cast<float4*>(op + 4) = make_float4(a2[4], a2[5], a2[6], a2[7]);
    }
}

// ---------------- stream/event resources (created once at static init) ----------------
struct GraphRes {
    cudaStream_t s1;
    cudaEvent_t ev0, ev_enc, ev_gi1, ev_gu1, ev_ci1, ev_cu1;
    GraphRes() {
        cudaStreamCreateWithFlags(&s1, cudaStreamNonBlocking);
        cudaEventCreateWithFlags(&ev0,    cudaEventDisableTiming);
        cudaEventCreateWithFlags(&ev_enc, cudaEventDisableTiming);
        cudaEventCreateWithFlags(&ev_gi1, cudaEventDisableTiming);
        cudaEventCreateWithFlags(&ev_gu1, cudaEventDisableTiming);
        cudaEventCreateWithFlags(&ev_ci1, cudaEventDisableTiming);
        cudaEventCreateWithFlags(&ev_cu1, cudaEventDisableTiming);
    }
};
static GraphRes g_res;

// ---------------- launch ----------------
static float* sym_addr_f(const void* sym) {
    void* p = nullptr;
    cudaGetSymbolAddress(&p, sym);
    return reinterpret_cast<float*>(p);
}
static int* sym_addr_i(const void* sym) {
    void* p = nullptr;
    cudaGetSymbolAddress(&p, sym);
    return reinterpret_cast<int*>(p);
}

extern "C" void kernel_launch(void* const* d_in, const int* in_sizes, int n_in,
                              void* d_out, int out_size)
{
    const float* x_user  = (const float*)d_in[0];
    const float* x_item  = (const float*)d_in[1];
    const int*   ei_u2i  = (const int*)d_in[2];
    const int*   ei_i2u  = (const int*)d_in[3];
    const float* enc_uw  = (const float*)d_in[4];
    const float* enc_ub  = (const float*)d_in[5];
    const float* enc_iw  = (const float*)d_in[6];
    const float* enc_ib  = (const float*)d_in[7];
    const float* L[12];
    for (int i = 0; i < 12; i++) L[i] = (const float*)d_in[8 + i];
    const float* head_w1 = (const float*)d_in[20];
    const float* head_b1 = (const float*)d_in[21];
    const float* head_w2 = (const float*)d_in[22];
    const float* head_b2 = (const float*)d_in[23];
    float* out = (float*)d_out;

    float* hu     = sym_addr_f(g_hu);
    float* hi     = sym_addr_f(g_hi);
    float* hu2    = sym_addr_f(g_hu2);
    float* hi2    = sym_addr_f(g_hi2);
    float* agg_i  = sym_addr_f(g_aggi);
    float* agg_u  = sym_addr_f(g_aggu);
    float* agg_u2 = sym_addr_f(g_aggu2);

    int* deg    = sym_addr_i(g_deg);
    int* rowptr = sym_addr_i(g_rowptr);
    int* fill   = sym_addr_i(g_fill);
    int* bsums  = sym_addr_i(g_bsums);
    int* esrc   = sym_addr_i(g_esrc);

    cudaStream_t s1 = g_res.s1;
    const int EBV = (NE + 255) / 256;        // 2-edges-per-thread grids
    const int NB1 = (NN + 1023) / 1024;

    // ---- fork: encoders on s1, CSR build on main ----
    cudaEventRecord(g_res.ev0, 0);
    cudaStreamWaitEvent(s1, g_res.ev0, 0);

    mlp_relu_kernel<64, 128><<<(NU + 63) / 64, 128, 0, s1>>>(x_user, enc_uw, enc_ub, hu, NU);
    mlp_relu_kernel<32, 128><<<(NI + 63) / 64, 128, 0, s1>>>(x_item, enc_iw, enc_ib, hi, NI);
    cudaEventRecord(g_res.ev_enc, s1);

    zero_kernel<<<(NN / 4 + 255) / 256, 256>>>((float4*)deg, NN / 4);
    hist2_kernel<<<EBV, 256>>>(ei_u2i, ei_i2u, deg);
    scan1_kernel<<<NB1, 1024>>>(deg, rowptr, bsums, NN);
    scan2_kernel<<<1, 1024>>>(bsums, NB1);
    scan3_kernel<<<(NN + 255) / 256, 256>>>(rowptr, fill, bsums, NN, 2 * NE);
    fill2_kernel<<<EBV, 256>>>(ei_u2i, ei_i2u, fill, esrc);

    // ---- layer 1 gathers, serial on main (each at full L2 bandwidth) ----
    cudaStreamWaitEvent(0, g_res.ev_enc, 0);
    gather_mean_kernel<<<(NI * 32 + 255) / 256, 256>>>(hu, rowptr, esrc, agg_i, NI);
    cudaEventRecord(g_res.ev_gi1, 0);
    gather_mean_kernel<<<(NU * 32 + 255) / 256, 256>>>(hi, rowptr + NI, esrc, agg_u, NU);
    cudaEventRecord(g_res.ev_gu1, 0);

    // ---- c_i1 on s1 (fma) overlaps gather_u1 (L2): reads hi (read-read OK), writes hi2 ----
    cudaStreamWaitEvent(s1, g_res.ev_gi1, 0);
    combine_kernel<<<(NI + 63) / 64, 128, 0, s1>>>(agg_i, hi, hi2, L[0], L[1], L[2], NI);
    cudaEventRecord(g_res.ev_ci1, s1);

    // ---- c_u1 on s1 (fma) overlaps gather_u2 (L2): writes hu2 ----
    cudaStreamWaitEvent(s1, g_res.ev_gu1, 0);
    combine_kernel<<<(NU + 63) / 64, 128, 0, s1>>>(agg_u, hu, hu2, L[3], L[4], L[5], NU);
    cudaEventRecord(g_res.ev_cu1, s1);

    // ---- layer 2 user gather on main: reads hi2 (after c_i1), writes agg_u2 ----
    cudaStreamWaitEvent(0, g_res.ev_ci1, 0);
    gather_mean_kernel<<<(NU * 32 + 255) / 256, 256>>>(hi2, rowptr + NI, esrc, agg_u2, NU);

    // ---- c_u2 on main: needs agg_u2 + hu2 (from c_u1); in-place on hu2 ----
    cudaStreamWaitEvent(0, g_res.ev_cu1, 0);
    combine_kernel<<<(NU + 63) / 64, 128>>>(agg_u2, hu2, hu2, L[9], L[10], L[11], NU);

    // ---- fused head ----
    head_fused_kernel<<<(NU + 127) / 128, 128>>>(hu2, head_w1, head_b1, head_w2, head_b2, out, NU);
}